// round 8
// baseline (speedup 1.0000x reference)
#include <cuda_runtime.h>
#include <cstdint>

// x: [8192, 4096] fp32 row-major. loss = N*sum(x*x) - sum_d(colsum_d)^2
#define N_ROWS   8192
#define D_COLS   4096
#define ROW_F4   (D_COLS / 4)               // 1024 float4 per row

// Phase-1 geometry: EXACTLY R1's k1 (measured 24.8us @ 70.3% DRAM)
#define CBLK     4                          // column groups, 1024 cols each
#define RCHUNKS  128                        // row chunks
#define ROWS_PER_CHUNK (N_ROWS / RCHUNKS)   // 64
#define NBLOCKS  (CBLK * RCHUNKS)           // 512
#define NTHREADS 256

// Deputy-chain tail
#define SUPER    16                         // chunks per super-group
#define NSUPER   (RCHUNKS / SUPER)          // 8 super-groups

// Scratch (__device__ globals; no allocations allowed)
__device__ float    g_part [RCHUNKS * D_COLS];        // 2 MB level-1 colsum partials
__device__ float    g_part2[CBLK * NSUPER * 1024];    // 128 KB level-2 (per cg,sg: 1024 cols)
__device__ float    g_ss_part[NBLOCKS];               // 512 sumsq partials
__device__ float    g_colsq[CBLK];
__device__ unsigned g_cnt_super[CBLK * NSUPER];       // each resets itself after firing
__device__ unsigned g_cnt_cg[CBLK];
__device__ unsigned g_cnt_final;

// block-reduce one float over 256 threads -> valid in thread 0
__device__ __forceinline__ float block_sum(float v, float* sh8, int t) {
    #pragma unroll
    for (int o = 16; o > 0; o >>= 1) v += __shfl_down_sync(0xffffffffu, v, o);
    if ((t & 31) == 0) sh8[t >> 5] = v;
    __syncthreads();
    float r = 0.f;
    if (t < 8) {
        r = sh8[t];
        #pragma unroll
        for (int o = 4; o > 0; o >>= 1) r += __shfl_down_sync(0xffu, r, o);
    }
    __syncthreads();
    return r;
}

__global__ __launch_bounds__(NTHREADS, 8)
void stability_loss_kernel(const float* __restrict__ x, float* __restrict__ out)
{
    __shared__ float    sh_red[8];
    __shared__ unsigned sh_old;

    const int t     = threadIdx.x;
    const int cg    = blockIdx.x;           // 0..3   (column group)
    const int chunk = blockIdx.y;           // 0..127 (row chunk)
    const int sg    = chunk >> 4;           // super-group 0..7

    // ---------------- Phase 1: R1's k1 body, unchanged ----------------
    {
        const int col = cg * (NTHREADS * 4) + t * 4;
        const int r0  = chunk * ROWS_PER_CHUNK;

        const float4* __restrict__ p =
            reinterpret_cast<const float4*>(x + (size_t)r0 * D_COLS + col);

        float4 cs = make_float4(0.f, 0.f, 0.f, 0.f);
        float  ss = 0.f;

        #pragma unroll 8
        for (int r = 0; r < ROWS_PER_CHUNK; ++r) {
            float4 v = p[(size_t)r * ROW_F4];
            cs.x += v.x; cs.y += v.y; cs.z += v.z; cs.w += v.w;
            ss   += v.x*v.x + v.y*v.y + v.z*v.z + v.w*v.w;
        }

        reinterpret_cast<float4*>(g_part + (size_t)chunk * D_COLS)
            [cg * NTHREADS + t] = cs;

        float tot = block_sum(ss, sh_red, t);
        if (t == 0) g_ss_part[chunk * CBLK + cg] = tot;
    }

    // ---------------- Level 1 -> 2: last arrival of (cg,sg)'s 16 chunks ----------------
    __threadfence();
    if (t == 0) sh_old = atomicAdd(&g_cnt_super[cg * NSUPER + sg], 1u);
    __syncthreads();
    if (sh_old != SUPER - 1) return;
    if (t == 0) g_cnt_super[cg * NSUPER + sg] = 0;   // reset for next graph replay

    {
        const float4* P = reinterpret_cast<const float4*>(g_part);
        float4 s = make_float4(0.f, 0.f, 0.f, 0.f);
        #pragma unroll 4
        for (int c = 0; c < SUPER; ++c) {
            float4 v = __ldcg(&P[(size_t)(sg * SUPER + c) * ROW_F4 + cg * NTHREADS + t]);
            s.x += v.x; s.y += v.y; s.z += v.z; s.w += v.w;
        }
        reinterpret_cast<float4*>(g_part2)[(size_t)(cg * NSUPER + sg) * NTHREADS + t] = s;
    }

    // ---------------- Level 2 -> colsq: last super-deputy of this cg ----------------
    __threadfence();
    __syncthreads();
    if (t == 0) sh_old = atomicAdd(&g_cnt_cg[cg], 1u);
    __syncthreads();
    if (sh_old != NSUPER - 1) return;
    if (t == 0) g_cnt_cg[cg] = 0;

    {
        const float4* P2 = reinterpret_cast<const float4*>(g_part2);
        float4 s = make_float4(0.f, 0.f, 0.f, 0.f);
        #pragma unroll
        for (int sgi = 0; sgi < NSUPER; ++sgi) {
            float4 v = __ldcg(&P2[(size_t)(cg * NSUPER + sgi) * NTHREADS + t]);
            s.x += v.x; s.y += v.y; s.z += v.z; s.w += v.w;
        }
        float sq = s.x*s.x + s.y*s.y + s.z*s.z + s.w*s.w;
        float csq = block_sum(sq, sh_red, t);
        if (t == 0) g_colsq[cg] = csq;
    }

    // ---------------- Final: last cg-deputy folds everything ----------------
    __threadfence();
    __syncthreads();
    if (t == 0) sh_old = atomicAdd(&g_cnt_final, 1u);
    __syncthreads();
    if (sh_old != CBLK - 1) return;
    if (t == 0) g_cnt_final = 0;

    {
        float ss = __ldcg(&g_ss_part[t]) + __ldcg(&g_ss_part[t + 256]);
        float cq = (t < CBLK) ? __ldcg(&g_colsq[t]) : 0.f;

        #pragma unroll
        for (int o = 16; o > 0; o >>= 1) {
            ss += __shfl_down_sync(0xffffffffu, ss, o);
            cq += __shfl_down_sync(0xffffffffu, cq, o);
        }
        __shared__ float sh_a[8], sh_b[8];
        if ((t & 31) == 0) { sh_a[t >> 5] = ss; sh_b[t >> 5] = cq; }
        __syncthreads();
        if (t < 8) {
            float a = sh_a[t], c2 = sh_b[t];
            #pragma unroll
            for (int o = 4; o > 0; o >>= 1) {
                a  += __shfl_down_sync(0xffu, a,  o);
                c2 += __shfl_down_sync(0xffu, c2, o);
            }
            if (t == 0)
                out[0] = (float)N_ROWS * a - c2;
        }
    }
}

extern "C" void kernel_launch(void* const* d_in, const int* in_sizes, int n_in,
                              void* d_out, int out_size)
{
    const float* x = (const float*)d_in[0];
    float* out = (float*)d_out;
    (void)in_sizes; (void)n_in; (void)out_size;

    dim3 grid(CBLK, RCHUNKS);
    stability_loss_kernel<<<grid, NTHREADS>>>(x, out);
}